// round 1
// baseline (speedup 1.0000x reference)
#include <cuda_runtime.h>

#define H 1024
#define W 1024
#define NB 16
#define TILE 64
#define HALO 5
#define BUF 74      // TILE + 2*HALO
#define ER  72      // erode compute region (T+4)
#define NTHREADS 256

// accumulators: [0]=A Σskel_p*t, [1]=B Σskel_p, [2]=C Σskel_t*p, [3]=D Σskel_t,
// [4+b]=inter_b, [20+b]=sum_sig_p_b, [36+b]=sum_t_b
__device__ double g_acc[52];

__device__ __forceinline__ float gelu_f(float x) {
    // exact (erf) gelu, matches jax.nn.gelu(approximate=False)
    return x * 0.5f * (1.0f + erff(x * 0.70710678118654752440f));
}

__global__ void zero_acc_kernel() {
    int i = threadIdx.x;
    if (i < 52) g_acc[i] = 0.0;
}

__global__ __launch_bounds__(NTHREADS)
void cldice_main(const float* __restrict__ y_pred, const float* __restrict__ y_true) {
    __shared__ float bufA[BUF * BUF];
    __shared__ float bufB[BUF * BUF];
    __shared__ float red[8][8];

    const int tid = threadIdx.x;
    const int bx = blockIdx.x, by = blockIdx.y, b = blockIdx.z;
    const int gx0 = bx * TILE, gy0 = by * TILE;
    const int base = b * (H * W);

    const int tx  = tid & 63;   // column within tile
    const int ty0 = tid >> 6;   // 0..3

    float skel[16], pv[16], tv[16];
    float accA = 0.f, accB = 0.f, accC = 0.f, accD = 0.f;
    float accI = 0.f, accP = 0.f, accT = 0.f;

    const float INF = __int_as_float(0x7f800000);

    #pragma unroll 1
    for (int t = 0; t < 2; ++t) {
        const float* src = (t == 0) ? y_pred : y_true;
        float* b0 = bufA;
        float* b1 = bufB;

        // ---- load 74x74 halo tile; out-of-image -> +INF sentinel ----
        for (int i = tid; i < BUF * BUF; i += NTHREADS) {
            int sy = i / BUF, sx = i - sy * BUF;
            int gy = gy0 - HALO + sy, gx = gx0 - HALO + sx;
            bool ok = (gy >= 0) & (gy < H) & (gx >= 0) & (gx < W);
            b0[i] = ok ? __ldg(src + base + gy * W + gx) : INF;
        }
        __syncthreads();

        #pragma unroll 1
        for (int lvl = 0; lvl < 4; ++lvl) {
            // ---- erode (plus-shaped min) b0 -> b1 on [1..72]^2 ----
            for (int i = tid; i < ER * ER; i += NTHREADS) {
                int y = 1 + i / ER;
                int x = 1 + (i - (y - 1) * ER);
                const float* r = b0 + y * BUF + x;
                float v = fminf(r[0], r[-1]);
                v = fminf(v, r[1]);
                v = fminf(v, r[-BUF]);
                v = fminf(v, r[BUF]);
                int gy = gy0 - HALO + y, gx = gx0 - HALO + x;
                bool ok = (gy >= 0) & (gy < H) & (gx >= 0) & (gx < W);
                b1[y * BUF + x] = ok ? v : INF;
            }
            __syncthreads();

            // ---- dilate(b1) 3x3 + delta + skel update on the 64x64 tile ----
            #pragma unroll 4
            for (int j = 0; j < 16; ++j) {
                int ty = j * 4 + ty0;
                int sy = ty + HALO, sx = tx + HALO;
                const float* r = b1 + sy * BUF + sx;
                float m = -INF;
                #pragma unroll
                for (int dy = -1; dy <= 1; ++dy) {
                    #pragma unroll
                    for (int dx = -1; dx <= 1; ++dx) {
                        float v = r[dy * BUF + dx];
                        m = fmaxf(m, (v < 1e30f) ? v : -INF);  // +INF sentinel => ignore
                    }
                }
                float a = b0[sy * BUF + sx];      // img_lvl at this pixel
                float delta = gelu_f(a - m);      // gelu(img - open(img))
                if (lvl == 0) {
                    skel[j] = delta;
                    if (t == 0) {
                        pv[j] = a;
                        float tval = __ldg(y_true + base + (gy0 + ty) * W + gx0 + tx);
                        tv[j] = tval;
                        float s = 1.0f / (1.0f + __expf(-a));   // sigmoid(pred)
                        accI += s * tval;
                        accP += s;
                        accT += tval;
                    }
                } else {
                    skel[j] += gelu_f(delta - skel[j] * delta);
                }
            }
            __syncthreads();
            float* tmp = b0; b0 = b1; b1 = tmp;
        }

        if (t == 0) {
            #pragma unroll
            for (int j = 0; j < 16; ++j) { accA += skel[j] * tv[j]; accB += skel[j]; }
        } else {
            #pragma unroll
            for (int j = 0; j < 16; ++j) { accC += skel[j] * pv[j]; accD += skel[j]; }
        }
    }

    // ---- block reduction of 7 partials, then one double atomic each ----
    float vals[7] = {accA, accB, accC, accD, accI, accP, accT};
    int lane = tid & 31, warp = tid >> 5;
    #pragma unroll
    for (int k = 0; k < 7; ++k) {
        float v = vals[k];
        #pragma unroll
        for (int o = 16; o > 0; o >>= 1) v += __shfl_down_sync(0xffffffffu, v, o);
        if (lane == 0) red[warp][k] = v;
    }
    __syncthreads();
    if (warp == 0 && lane < 7) {
        float s = 0.f;
        #pragma unroll
        for (int w = 0; w < 8; ++w) s += red[w][lane];
        int idx = (lane < 4) ? lane : (4 + (lane - 4) * 16 + b);
        atomicAdd(&g_acc[idx], (double)s);
    }
}

__global__ void finalize_kernel(float* out, int n) {
    if (threadIdx.x == 0) {
        double A = g_acc[0], B = g_acc[1], C = g_acc[2], D = g_acc[3];
        double tprec = (A + 1.0) / (B + 1.0);
        double tsens = (C + 1.0) / (D + 1.0);
        double cl = 1.0 - 2.0 * (tprec * tsens) / (tprec + tsens);
        double dsum = 0.0;
        for (int i = 0; i < 16; ++i) {
            double gd = (2.0 * g_acc[4 + i] + 1e-4) / (g_acc[20 + i] + g_acc[36 + i] + 1e-4);
            dsum += 1.0 - gd;
        }
        double dice = dsum / 16.0;
        double res = 0.5 * cl + 0.5 * dice;
        for (int i = 0; i < n; ++i) out[i] = (float)res;
    }
}

extern "C" void kernel_launch(void* const* d_in, const int* in_sizes, int n_in,
                              void* d_out, int out_size) {
    const float* y_pred = (const float*)d_in[0];
    const float* y_true = (const float*)d_in[1];
    (void)in_sizes; (void)n_in;

    zero_acc_kernel<<<1, 64>>>();
    dim3 grid(W / TILE, H / TILE, NB);
    cldice_main<<<grid, NTHREADS>>>(y_pred, y_true);
    finalize_kernel<<<1, 32>>>((float*)d_out, out_size);
}

// round 3
// speedup vs baseline: 1.0967x; 1.0967x over previous
#include <cuda_runtime.h>

#define H 1024
#define W 1024
#define NB 16
#define TILE 64
#define XOFF 8          // tile col 0 sits at buffer x=8 (so tile cols are 4-aligned)
#define YOFF 5
#define SX 80           // buffer row stride (floats)
#define NROWS 74
#define NTHREADS 256

// accumulators: [0]=A sum skel_p*t, [1]=B sum skel_p, [2]=C sum skel_t*p, [3]=D sum skel_t,
// [4+b]=inter_b, [20+b]=sum_sig_p_b, [36+b]=sum_t_b
__device__ double g_acc[52];

__device__ __forceinline__ float gelu_f(float x) {
    // exact (erf) gelu, matches jax.nn.gelu(approximate=False)
    return x * 0.5f * (1.0f + erff(x * 0.70710678118654752440f));
}

__global__ void zero_acc_kernel() {
    int i = threadIdx.x;
    if (i < 52) g_acc[i] = 0.0;
}

__global__ __launch_bounds__(NTHREADS, 2)
void cldice_main(const float* __restrict__ y_pred, const float* __restrict__ y_true) {
    __shared__ float bufA[NROWS * SX];
    __shared__ float bufB[NROWS * SX];
    __shared__ float red[8][8];

    const int tid = threadIdx.x;
    const int gx0 = blockIdx.x * TILE, gy0 = blockIdx.y * TILE, b = blockIdx.z;
    const int base = b * (H * W);
    const bool bdry = (blockIdx.x == 0) | (blockIdx.x == (W/TILE - 1)) |
                      (blockIdx.y == 0) | (blockIdx.y == (H/TILE - 1));

    // 4x4 output block per thread: 16 blocks in x, 16 in y
    const int tx4 = tid & 15, ty4 = tid >> 4;
    const int sx = XOFF + tx4 * 4, sy = YOFF + ty4 * 4;

    // buffer coords valid iff gx0 + x - XOFF in [0,W) etc.
    const int xv_lo = XOFF - gx0;
    const int xv_hi = XOFF + (W - 1) - gx0;
    const int yv_lo = YOFF - gy0;
    const int yv_hi = YOFF + (H - 1) - gy0;

    float skel[16], pv[16], tv[16];
    float accA = 0.f, accB = 0.f, accC = 0.f, accD = 0.f;
    float accI = 0.f, accP = 0.f, accT = 0.f;

    const float INF = __int_as_float(0x7f800000);
    const float NINF = __int_as_float(0xff800000);

    #pragma unroll 1
    for (int t = 0; t < 2; ++t) {
        const float* src = t ? y_true : y_pred;
        float* b0 = bufA;
        float* b1 = bufB;

        // ---- load 74x74 halo tile into buffer x in [3,76], y in [0,73]; OOB -> +INF ----
        for (int i = tid; i < 74 * 74; i += NTHREADS) {
            int yy = i / 74, xx = i - yy * 74;
            int x = xx + 3;
            int gy = gy0 + yy - YOFF, gx = gx0 + x - XOFF;
            bool ok = (gy >= 0) & (gy < H) & (gx >= 0) & (gx < W);
            b0[yy * SX + x] = ok ? __ldg(src + base + gy * W + gx) : INF;
        }
        __syncthreads();

        #pragma unroll 1
        for (int lvl = 0; lvl < 4; ++lvl) {
            // ---- erode (plus-min), float4-vectorized ----
            // output region: y in [1+lvl, 72-lvl]; x chunks 4,8,...,72 (covers [4,75])
            const int yl = 1 + lvl;
            const int ny = 72 - 2 * lvl;
            for (int i = tid; i < ny * 18; i += NTHREADS) {
                int ry = i / 18;
                int x4 = 4 + (i - ry * 18) * 4;
                int y = yl + ry;
                const float* rc = b0 + y * SX + x4;
                float4 c = *(const float4*)rc;
                float4 u = *(const float4*)(rc - SX);
                float4 d = *(const float4*)(rc + SX);
                float lft = rc[-1], rgt = rc[4];
                float4 o;
                o.x = fminf(fminf(c.x, fminf(lft, c.y)), fminf(u.x, d.x));
                o.y = fminf(fminf(c.y, fminf(c.x, c.z)), fminf(u.y, d.y));
                o.z = fminf(fminf(c.z, fminf(c.y, c.w)), fminf(u.z, d.z));
                o.w = fminf(fminf(c.w, fminf(c.z, rgt)), fminf(u.w, d.w));
                *(float4*)(b1 + y * SX + x4) = o;
            }
            if (bdry) {
                __syncthreads();   // order erode writes before fixup overwrites
                // re-INF out-of-image positions within the e-region
                const int xl = 4 + lvl;
                const int w  = 72 - 2 * lvl;   // x in [xl, xl+w-1] == [4+lvl, 75-lvl]
                for (int i = tid; i < ny * w; i += NTHREADS) {
                    int ry = i / w;
                    int x = xl + (i - ry * w);
                    int y = yl + ry;
                    if ((x < xv_lo) | (x > xv_hi) | (y < yv_lo) | (y > yv_hi))
                        b1[y * SX + x] = INF;
                }
            }
            __syncthreads();

            // ---- dilate 3x3 (register-blocked 4x4) + delta + skel update ----
            float h[6][4];
            #pragma unroll
            for (int r = 0; r < 6; ++r) {
                const float* row = b1 + (sy - 1 + r) * SX + sx;
                float4 c = *(const float4*)row;
                float lf = row[-1], rg = row[4];
                if (bdry) {
                    // +INF sentinel (out-of-image) must be neutral for max
                    lf  = (lf  < 1e30f) ? lf  : NINF;
                    c.x = (c.x < 1e30f) ? c.x : NINF;
                    c.y = (c.y < 1e30f) ? c.y : NINF;
                    c.z = (c.z < 1e30f) ? c.z : NINF;
                    c.w = (c.w < 1e30f) ? c.w : NINF;
                    rg  = (rg  < 1e30f) ? rg  : NINF;
                }
                h[r][0] = fmaxf(lf,  fmaxf(c.x, c.y));
                h[r][1] = fmaxf(c.x, fmaxf(c.y, c.z));
                h[r][2] = fmaxf(c.y, fmaxf(c.z, c.w));
                h[r][3] = fmaxf(c.z, fmaxf(c.w, rg));
            }
            #pragma unroll
            for (int r = 0; r < 4; ++r) {
                const float4 a4 = *(const float4*)(b0 + (sy + r) * SX + sx);
                float av[4] = {a4.x, a4.y, a4.z, a4.w};
                float4 t4;
                if (lvl == 0 && t == 0) {
                    t4 = *(const float4*)(y_true + base + (gy0 + sy - YOFF + r) * W
                                          + gx0 + sx - XOFF);
                }
                #pragma unroll
                for (int c = 0; c < 4; ++c) {
                    float m = fmaxf(h[r][c], fmaxf(h[r + 1][c], h[r + 2][c]));
                    float a = av[c];
                    float delta = gelu_f(a - m);
                    int j = r * 4 + c;
                    if (lvl == 0) {
                        skel[j] = delta;
                        if (t == 0) {
                            pv[j] = a;
                            float tval = (c == 0) ? t4.x : (c == 1) ? t4.y
                                       : (c == 2) ? t4.z : t4.w;
                            tv[j] = tval;
                            float s = 1.0f / (1.0f + __expf(-a));
                            accI += s * tval;
                            accP += s;
                            accT += tval;
                        }
                    } else {
                        skel[j] += gelu_f(delta - skel[j] * delta);
                    }
                }
            }
            __syncthreads();
            float* tmp = b0; b0 = b1; b1 = tmp;
        }

        if (t == 0) {
            #pragma unroll
            for (int j = 0; j < 16; ++j) { accA += skel[j] * tv[j]; accB += skel[j]; }
        } else {
            #pragma unroll
            for (int j = 0; j < 16; ++j) { accC += skel[j] * pv[j]; accD += skel[j]; }
        }
    }

    // ---- block reduction of 7 partials, then one double atomic each ----
    float vals[7] = {accA, accB, accC, accD, accI, accP, accT};
    int lane = tid & 31, warp = tid >> 5;
    #pragma unroll
    for (int k = 0; k < 7; ++k) {
        float v = vals[k];
        #pragma unroll
        for (int o = 16; o > 0; o >>= 1) v += __shfl_down_sync(0xffffffffu, v, o);
        if (lane == 0) red[warp][k] = v;
    }
    __syncthreads();
    if (warp == 0 && lane < 7) {
        float s = 0.f;
        #pragma unroll
        for (int w = 0; w < 8; ++w) s += red[w][lane];
        int idx = (lane < 4) ? lane : (4 + (lane - 4) * 16 + b);
        atomicAdd(&g_acc[idx], (double)s);
    }
}

__global__ void finalize_kernel(float* out, int n) {
    if (threadIdx.x == 0) {
        double A = g_acc[0], B = g_acc[1], C = g_acc[2], D = g_acc[3];
        double tprec = (A + 1.0) / (B + 1.0);
        double tsens = (C + 1.0) / (D + 1.0);
        double cl = 1.0 - 2.0 * (tprec * tsens) / (tprec + tsens);
        double dsum = 0.0;
        for (int i = 0; i < 16; ++i) {
            double gd = (2.0 * g_acc[4 + i] + 1e-4) / (g_acc[20 + i] + g_acc[36 + i] + 1e-4);
            dsum += 1.0 - gd;
        }
        double dice = dsum / 16.0;
        double res = 0.5 * cl + 0.5 * dice;
        for (int i = 0; i < n; ++i) out[i] = (float)res;
    }
}

extern "C" void kernel_launch(void* const* d_in, const int* in_sizes, int n_in,
                              void* d_out, int out_size) {
    const float* y_pred = (const float*)d_in[0];
    const float* y_true = (const float*)d_in[1];
    (void)in_sizes; (void)n_in;

    zero_acc_kernel<<<1, 64>>>();
    dim3 grid(W / TILE, H / TILE, NB);
    cldice_main<<<grid, NTHREADS>>>(y_pred, y_true);
    finalize_kernel<<<1, 32>>>((float*)d_out, out_size);
}

// round 4
// speedup vs baseline: 1.3731x; 1.2520x over previous
#include <cuda_runtime.h>

#define H 1024
#define W 1024
#define NB 16
#define TILE 64
#define XOFF 8          // tile col 0 sits at buffer x=8 (so tile cols are 4-aligned)
#define YOFF 5
#define SX 80           // buffer row stride (floats)
#define NROWS 74
#define NTHREADS 256

// accumulators: [0]=A sum skel_p*t, [1]=B sum skel_p, [2]=C sum skel_t*p, [3]=D sum skel_t,
// [4+b]=inter_b, [20+b]=sum_sig_p_b, [36+b]=sum_t_b
__device__ double g_acc[52];

__device__ __forceinline__ float ex2_approx(float x) {
    float r;
    asm("ex2.approx.ftz.f32 %0, %1;" : "=f"(r) : "f"(x));
    return r;
}
__device__ __forceinline__ float rcp_approx(float x) {
    float r;
    asm("rcp.approx.ftz.f32 %0, %1;" : "=f"(r) : "f"(x));
    return r;
}

__device__ __forceinline__ float gelu_f(float x) {
    // tanh-form gelu via EX2: gelu(x) ~= x * sigmoid(2*0.7978845608*(x + 0.044715 x^3))
    //   = x * rcp(1 + exp2(x * (c0 + c1*x^2)))
    // c0 = -2*0.7978845608*log2(e) = -2.302118149, c1 = c0*0.044715 = -0.1029392175
    // Branchless; saturates correctly: x->+inf => exp2->0 => gelu=x; x->-inf => exp2->inf => gelu=0.
    float x2 = x * x;
    float arg = x * fmaf(-0.1029392175f, x2, -2.302118149f);
    float den = ex2_approx(arg) + 1.0f;
    return x * rcp_approx(den);
}

__device__ __forceinline__ float sigmoid_f(float x) {
    // 1/(1+e^-x) = rcp(1 + exp2(-x*log2(e)))
    float den = ex2_approx(x * -1.442695041f) + 1.0f;
    return rcp_approx(den);
}

__global__ void zero_acc_kernel() {
    int i = threadIdx.x;
    if (i < 52) g_acc[i] = 0.0;
}

__global__ __launch_bounds__(NTHREADS, 2)
void cldice_main(const float* __restrict__ y_pred, const float* __restrict__ y_true) {
    __shared__ float bufA[NROWS * SX];
    __shared__ float bufB[NROWS * SX];
    __shared__ float red[8][8];

    const int tid = threadIdx.x;
    const int gx0 = blockIdx.x * TILE, gy0 = blockIdx.y * TILE, b = blockIdx.z;
    const int base = b * (H * W);
    const bool bdry = (blockIdx.x == 0) | (blockIdx.x == (W/TILE - 1)) |
                      (blockIdx.y == 0) | (blockIdx.y == (H/TILE - 1));

    // 4x4 output block per thread: 16 blocks in x, 16 in y
    const int tx4 = tid & 15, ty4 = tid >> 4;
    const int sx = XOFF + tx4 * 4, sy = YOFF + ty4 * 4;

    // buffer coords valid iff gx0 + x - XOFF in [0,W) etc.
    const int xv_lo = XOFF - gx0;
    const int xv_hi = XOFF + (W - 1) - gx0;
    const int yv_lo = YOFF - gy0;
    const int yv_hi = YOFF + (H - 1) - gy0;

    float skel[16], pv[16], tv[16];
    float accA = 0.f, accB = 0.f, accC = 0.f, accD = 0.f;
    float accI = 0.f, accP = 0.f, accT = 0.f;

    const float INF = __int_as_float(0x7f800000);
    const float NINF = __int_as_float(0xff800000);

    #pragma unroll 1
    for (int t = 0; t < 2; ++t) {
        const float* src = t ? y_true : y_pred;
        float* b0 = bufA;
        float* b1 = bufB;

        // ---- load 74x74 halo tile into buffer x in [3,76], y in [0,73]; OOB -> +INF ----
        for (int i = tid; i < 74 * 74; i += NTHREADS) {
            int yy = i / 74, xx = i - yy * 74;
            int x = xx + 3;
            int gy = gy0 + yy - YOFF, gx = gx0 + x - XOFF;
            bool ok = (gy >= 0) & (gy < H) & (gx >= 0) & (gx < W);
            b0[yy * SX + x] = ok ? __ldg(src + base + gy * W + gx) : INF;
        }
        __syncthreads();

        #pragma unroll 1
        for (int lvl = 0; lvl < 4; ++lvl) {
            // ---- erode (plus-min), float4-vectorized ----
            // output region: y in [1+lvl, 72-lvl]; x chunks 4,8,...,72 (covers [4,75])
            const int yl = 1 + lvl;
            const int ny = 72 - 2 * lvl;
            for (int i = tid; i < ny * 18; i += NTHREADS) {
                int ry = i / 18;
                int x4 = 4 + (i - ry * 18) * 4;
                int y = yl + ry;
                const float* rc = b0 + y * SX + x4;
                float4 c = *(const float4*)rc;
                float4 u = *(const float4*)(rc - SX);
                float4 d = *(const float4*)(rc + SX);
                float lft = rc[-1], rgt = rc[4];
                float4 o;
                o.x = fminf(fminf(c.x, fminf(lft, c.y)), fminf(u.x, d.x));
                o.y = fminf(fminf(c.y, fminf(c.x, c.z)), fminf(u.y, d.y));
                o.z = fminf(fminf(c.z, fminf(c.y, c.w)), fminf(u.z, d.z));
                o.w = fminf(fminf(c.w, fminf(c.z, rgt)), fminf(u.w, d.w));
                *(float4*)(b1 + y * SX + x4) = o;
            }
            if (bdry) {
                __syncthreads();   // order erode writes before fixup overwrites
                // re-INF out-of-image positions within the e-region
                const int xl = 4 + lvl;
                const int w  = 72 - 2 * lvl;   // x in [xl, xl+w-1] == [4+lvl, 75-lvl]
                for (int i = tid; i < ny * w; i += NTHREADS) {
                    int ry = i / w;
                    int x = xl + (i - ry * w);
                    int y = yl + ry;
                    if ((x < xv_lo) | (x > xv_hi) | (y < yv_lo) | (y > yv_hi))
                        b1[y * SX + x] = INF;
                }
            }
            __syncthreads();

            // ---- dilate 3x3 (register-blocked 4x4) + delta + skel update ----
            float h[6][4];
            #pragma unroll
            for (int r = 0; r < 6; ++r) {
                const float* row = b1 + (sy - 1 + r) * SX + sx;
                float4 c = *(const float4*)row;
                float lf = row[-1], rg = row[4];
                if (bdry) {
                    // +INF sentinel (out-of-image) must be neutral for max
                    lf  = (lf  < 1e30f) ? lf  : NINF;
                    c.x = (c.x < 1e30f) ? c.x : NINF;
                    c.y = (c.y < 1e30f) ? c.y : NINF;
                    c.z = (c.z < 1e30f) ? c.z : NINF;
                    c.w = (c.w < 1e30f) ? c.w : NINF;
                    rg  = (rg  < 1e30f) ? rg  : NINF;
                }
                h[r][0] = fmaxf(lf,  fmaxf(c.x, c.y));
                h[r][1] = fmaxf(c.x, fmaxf(c.y, c.z));
                h[r][2] = fmaxf(c.y, fmaxf(c.z, c.w));
                h[r][3] = fmaxf(c.z, fmaxf(c.w, rg));
            }
            #pragma unroll
            for (int r = 0; r < 4; ++r) {
                const float4 a4 = *(const float4*)(b0 + (sy + r) * SX + sx);
                float av[4] = {a4.x, a4.y, a4.z, a4.w};
                float4 t4;
                if (lvl == 0 && t == 0) {
                    t4 = *(const float4*)(y_true + base + (gy0 + sy - YOFF + r) * W
                                          + gx0 + sx - XOFF);
                }
                #pragma unroll
                for (int c = 0; c < 4; ++c) {
                    float m = fmaxf(h[r][c], fmaxf(h[r + 1][c], h[r + 2][c]));
                    float a = av[c];
                    float delta = gelu_f(a - m);
                    int j = r * 4 + c;
                    if (lvl == 0) {
                        skel[j] = delta;
                        if (t == 0) {
                            pv[j] = a;
                            float tval = (c == 0) ? t4.x : (c == 1) ? t4.y
                                       : (c == 2) ? t4.z : t4.w;
                            tv[j] = tval;
                            float s = sigmoid_f(a);
                            accI += s * tval;
                            accP += s;
                            accT += tval;
                        }
                    } else {
                        skel[j] += gelu_f(delta - skel[j] * delta);
                    }
                }
            }
            __syncthreads();
            float* tmp = b0; b0 = b1; b1 = tmp;
        }

        if (t == 0) {
            #pragma unroll
            for (int j = 0; j < 16; ++j) { accA += skel[j] * tv[j]; accB += skel[j]; }
        } else {
            #pragma unroll
            for (int j = 0; j < 16; ++j) { accC += skel[j] * pv[j]; accD += skel[j]; }
        }
    }

    // ---- block reduction of 7 partials, then one double atomic each ----
    float vals[7] = {accA, accB, accC, accD, accI, accP, accT};
    int lane = tid & 31, warp = tid >> 5;
    #pragma unroll
    for (int k = 0; k < 7; ++k) {
        float v = vals[k];
        #pragma unroll
        for (int o = 16; o > 0; o >>= 1) v += __shfl_down_sync(0xffffffffu, v, o);
        if (lane == 0) red[warp][k] = v;
    }
    __syncthreads();
    if (warp == 0 && lane < 7) {
        float s = 0.f;
        #pragma unroll
        for (int w = 0; w < 8; ++w) s += red[w][lane];
        int idx = (lane < 4) ? lane : (4 + (lane - 4) * 16 + b);
        atomicAdd(&g_acc[idx], (double)s);
    }
}

__global__ void finalize_kernel(float* out, int n) {
    if (threadIdx.x == 0) {
        double A = g_acc[0], B = g_acc[1], C = g_acc[2], D = g_acc[3];
        double tprec = (A + 1.0) / (B + 1.0);
        double tsens = (C + 1.0) / (D + 1.0);
        double cl = 1.0 - 2.0 * (tprec * tsens) / (tprec + tsens);
        double dsum = 0.0;
        for (int i = 0; i < 16; ++i) {
            double gd = (2.0 * g_acc[4 + i] + 1e-4) / (g_acc[20 + i] + g_acc[36 + i] + 1e-4);
            dsum += 1.0 - gd;
        }
        double dice = dsum / 16.0;
        double res = 0.5 * cl + 0.5 * dice;
        for (int i = 0; i < n; ++i) out[i] = (float)res;
    }
}

extern "C" void kernel_launch(void* const* d_in, const int* in_sizes, int n_in,
                              void* d_out, int out_size) {
    const float* y_pred = (const float*)d_in[0];
    const float* y_true = (const float*)d_in[1];
    (void)in_sizes; (void)n_in;

    zero_acc_kernel<<<1, 64>>>();
    dim3 grid(W / TILE, H / TILE, NB);
    cldice_main<<<grid, NTHREADS>>>(y_pred, y_true);
    finalize_kernel<<<1, 32>>>((float*)d_out, out_size);
}

// round 6
// speedup vs baseline: 1.6264x; 1.1844x over previous
#include <cuda_runtime.h>

#define H 1024
#define W 1024
#define NB 16
#define TILE 64
#define XOFF 8          // tile col 0 sits at buffer x=8 (so tile cols are 4-aligned)
#define YOFF 5
#define SX 80           // buffer row stride (floats)
#define NROWS 74
#define NTHREADS 256

// accumulators: [0]=A sum skel_p*t, [1]=B sum skel_p, [2]=C sum skel_t*p, [3]=D sum skel_t,
// [4+b]=inter_b, [20+b]=sum_sig_p_b, [36+b]=sum_t_b
__device__ double g_acc[52];

__device__ __forceinline__ float ex2_approx(float x) {
    float r;
    asm("ex2.approx.ftz.f32 %0, %1;" : "=f"(r) : "f"(x));
    return r;
}
__device__ __forceinline__ float rcp_approx(float x) {
    float r;
    asm("rcp.approx.ftz.f32 %0, %1;" : "=f"(r) : "f"(x));
    return r;
}

__device__ __forceinline__ float gelu_f(float x) {
    // tanh-form gelu via EX2: gelu(x) ~= x * sigmoid(2*0.7978845608*(x + 0.044715 x^3))
    //   = x * rcp(1 + exp2(x * (c0 + c1*x^2)))
    float x2 = x * x;
    float arg = x * fmaf(-0.1029392175f, x2, -2.302118149f);
    float den = ex2_approx(arg) + 1.0f;
    return x * rcp_approx(den);
}

__device__ __forceinline__ float sigmoid_f(float x) {
    float den = ex2_approx(x * -1.442695041f) + 1.0f;
    return rcp_approx(den);
}

__global__ void zero_acc_kernel() {
    int i = threadIdx.x;
    if (i < 52) g_acc[i] = 0.0;
}

__global__ __launch_bounds__(NTHREADS, 3)
void cldice_main(const float* __restrict__ y_pred, const float* __restrict__ y_true) {
    __shared__ float bufA[NROWS * SX];
    __shared__ float bufB[NROWS * SX];
    __shared__ float red[8][8];

    const int tid = threadIdx.x;
    const int gx0 = blockIdx.x * TILE, gy0 = blockIdx.y * TILE, b = blockIdx.z;
    const int base = b * (H * W);
    const bool bdry = (blockIdx.x == 0) | (blockIdx.x == (W/TILE - 1)) |
                      (blockIdx.y == 0) | (blockIdx.y == (H/TILE - 1));

    // 4x4 output block per thread: 16 blocks in x, 16 in y
    const int tx4 = tid & 15, ty4 = tid >> 4;
    const int sx = XOFF + tx4 * 4, sy = YOFF + ty4 * 4;

    // buffer coords valid iff gx0 + x - XOFF in [0,W) etc.
    const int xv_lo = XOFF - gx0;
    const int xv_hi = XOFF + (W - 1) - gx0;
    const int yv_lo = YOFF - gy0;
    const int yv_hi = YOFF + (H - 1) - gy0;

    float skel[16];
    float accA = 0.f, accB = 0.f, accC = 0.f, accD = 0.f;
    float accI = 0.f, accP = 0.f, accT = 0.f;

    const float INF = __int_as_float(0x7f800000);
    const float NINF = __int_as_float(0xff800000);

    #pragma unroll 1
    for (int t = 0; t < 2; ++t) {
        const float* src = t ? y_true : y_pred;
        float* b0 = bufA;
        float* b1 = bufB;

        // ---- load 74x74 halo tile into buffer x in [3,76], y in [0,73]; OOB -> +INF ----
        for (int i = tid; i < 74 * 74; i += NTHREADS) {
            int yy = i / 74, xx = i - yy * 74;
            int x = xx + 3;
            int gy = gy0 + yy - YOFF, gx = gx0 + x - XOFF;
            bool ok = (gy >= 0) & (gy < H) & (gx >= 0) & (gx < W);
            b0[yy * SX + x] = ok ? __ldg(src + base + gy * W + gx) : INF;
        }
        __syncthreads();

        #pragma unroll 1
        for (int lvl = 0; lvl < 4; ++lvl) {
            // ---- erode (plus-min), float4-vectorized ----
            const int yl = 1 + lvl;
            const int ny = 72 - 2 * lvl;
            for (int i = tid; i < ny * 18; i += NTHREADS) {
                int ry = i / 18;
                int x4 = 4 + (i - ry * 18) * 4;
                int y = yl + ry;
                const float* rc = b0 + y * SX + x4;
                float4 c = *(const float4*)rc;
                float4 u = *(const float4*)(rc - SX);
                float4 d = *(const float4*)(rc + SX);
                float lft = rc[-1], rgt = rc[4];
                float4 o;
                o.x = fminf(fminf(c.x, fminf(lft, c.y)), fminf(u.x, d.x));
                o.y = fminf(fminf(c.y, fminf(c.x, c.z)), fminf(u.y, d.y));
                o.z = fminf(fminf(c.z, fminf(c.y, c.w)), fminf(u.z, d.z));
                o.w = fminf(fminf(c.w, fminf(c.z, rgt)), fminf(u.w, d.w));
                *(float4*)(b1 + y * SX + x4) = o;
            }
            if (bdry) {
                __syncthreads();   // order erode writes before fixup overwrites
                const int xl = 4 + lvl;
                const int w  = 72 - 2 * lvl;
                for (int i = tid; i < ny * w; i += NTHREADS) {
                    int ry = i / w;
                    int x = xl + (i - ry * w);
                    int y = yl + ry;
                    if ((x < xv_lo) | (x > xv_hi) | (y < yv_lo) | (y > yv_hi))
                        b1[y * SX + x] = INF;
                }
            }
            __syncthreads();

            // ---- dilate 3x3 (register-blocked 4x4) + delta + skel update ----
            float h[6][4];
            #pragma unroll
            for (int r = 0; r < 6; ++r) {
                const float* row = b1 + (sy - 1 + r) * SX + sx;
                float4 c = *(const float4*)row;
                float lf = row[-1], rg = row[4];
                if (bdry) {
                    lf  = (lf  < 1e30f) ? lf  : NINF;
                    c.x = (c.x < 1e30f) ? c.x : NINF;
                    c.y = (c.y < 1e30f) ? c.y : NINF;
                    c.z = (c.z < 1e30f) ? c.z : NINF;
                    c.w = (c.w < 1e30f) ? c.w : NINF;
                    rg  = (rg  < 1e30f) ? rg  : NINF;
                }
                h[r][0] = fmaxf(lf,  fmaxf(c.x, c.y));
                h[r][1] = fmaxf(c.x, fmaxf(c.y, c.z));
                h[r][2] = fmaxf(c.y, fmaxf(c.z, c.w));
                h[r][3] = fmaxf(c.z, fmaxf(c.w, rg));
            }
            #pragma unroll
            for (int r = 0; r < 4; ++r) {
                const float4 a4 = *(const float4*)(b0 + (sy + r) * SX + sx);
                float av[4] = {a4.x, a4.y, a4.z, a4.w};
                float4 t4;
                if (lvl == 0 && t == 0) {
                    t4 = *(const float4*)(y_true + base + (gy0 + sy - YOFF + r) * W
                                          + gx0 + sx - XOFF);
                }
                #pragma unroll
                for (int c = 0; c < 4; ++c) {
                    float m = fmaxf(h[r][c], fmaxf(h[r + 1][c], h[r + 2][c]));
                    float a = av[c];
                    float delta = gelu_f(a - m);
                    int j = r * 4 + c;
                    if (lvl == 0) {
                        skel[j] = delta;
                        if (t == 0) {
                            float tval = (c == 0) ? t4.x : (c == 1) ? t4.y
                                       : (c == 2) ? t4.z : t4.w;
                            float s = sigmoid_f(a);
                            accI += s * tval;
                            accP += s;
                            accT += tval;
                        }
                    } else {
                        skel[j] += gelu_f(delta - skel[j] * delta);
                    }
                }
            }
            __syncthreads();
            float* tmp = b0; b0 = b1; b1 = tmp;
        }

        // ---- accumulate skel sums; partner image re-read from gmem (L2) ----
        const float* partner = t ? y_pred : y_true;
        #pragma unroll
        for (int r = 0; r < 4; ++r) {
            const float4 p4 = *(const float4*)(partner + base + (gy0 + sy - YOFF + r) * W
                                               + gx0 + sx - XOFF);
            float pvv[4] = {p4.x, p4.y, p4.z, p4.w};
            #pragma unroll
            for (int c = 0; c < 4; ++c) {
                int j = r * 4 + c;
                if (t == 0) { accA += skel[j] * pvv[c]; accB += skel[j]; }
                else        { accC += skel[j] * pvv[c]; accD += skel[j]; }
            }
        }
    }

    // ---- block reduction of 7 partials, then one double atomic each ----
    float vals[7] = {accA, accB, accC, accD, accI, accP, accT};
    int lane = tid & 31, warp = tid >> 5;
    #pragma unroll
    for (int k = 0; k < 7; ++k) {
        float v = vals[k];
        #pragma unroll
        for (int o = 16; o > 0; o >>= 1) v += __shfl_down_sync(0xffffffffu, v, o);
        if (lane == 0) red[warp][k] = v;
    }
    __syncthreads();
    if (warp == 0 && lane < 7) {
        float s = 0.f;
        #pragma unroll
        for (int w = 0; w < 8; ++w) s += red[w][lane];
        int idx = (lane < 4) ? lane : (4 + (lane - 4) * 16 + b);
        atomicAdd(&g_acc[idx], (double)s);
    }
}

__global__ void finalize_kernel(float* out, int n) {
    if (threadIdx.x == 0) {
        double A = g_acc[0], B = g_acc[1], C = g_acc[2], D = g_acc[3];
        double tprec = (A + 1.0) / (B + 1.0);
        double tsens = (C + 1.0) / (D + 1.0);
        double cl = 1.0 - 2.0 * (tprec * tsens) / (tprec + tsens);
        double dsum = 0.0;
        for (int i = 0; i < 16; ++i) {
            double gd = (2.0 * g_acc[4 + i] + 1e-4) / (g_acc[20 + i] + g_acc[36 + i] + 1e-4);
            dsum += 1.0 - gd;
        }
        double dice = dsum / 16.0;
        double res = 0.5 * cl + 0.5 * dice;
        for (int i = 0; i < n; ++i) out[i] = (float)res;
    }
}

extern "C" void kernel_launch(void* const* d_in, const int* in_sizes, int n_in,
                              void* d_out, int out_size) {
    const float* y_pred = (const float*)d_in[0];
    const float* y_true = (const float*)d_in[1];
    (void)in_sizes; (void)n_in;

    zero_acc_kernel<<<1, 64>>>();
    dim3 grid(W / TILE, H / TILE, NB);
    cldice_main<<<grid, NTHREADS>>>(y_pred, y_true);
    finalize_kernel<<<1, 32>>>((float*)d_out, out_size);
}

// round 7
// speedup vs baseline: 1.9894x; 1.2232x over previous
#include <cuda_runtime.h>

#define H 1024
#define W 1024
#define NB 16
#define TILE 64
#define XOFF 8          // tile col 0 sits at buffer x=8 (so tile cols are 4-aligned)
#define YOFF 5
#define SX 80           // buffer row stride (floats)
#define NROWS 74
#define NTHREADS 256

// accumulators: [0]=A sum skel_p*t, [1]=B sum skel_p, [2]=C sum skel_t*p, [3]=D sum skel_t,
// [4+b]=inter_b, [20+b]=sum_sig_p_b, [36+b]=sum_t_b
__device__ double g_acc[52];

__device__ __forceinline__ float ex2_approx(float x) {
    float r;
    asm("ex2.approx.ftz.f32 %0, %1;" : "=f"(r) : "f"(x));
    return r;
}
__device__ __forceinline__ float rcp_approx(float x) {
    float r;
    asm("rcp.approx.ftz.f32 %0, %1;" : "=f"(r) : "f"(x));
    return r;
}

__device__ __forceinline__ float gelu_f(float x) {
    // tanh-form gelu via EX2: gelu(x) ~= x * rcp(1 + exp2(x*(c0 + c1*x^2)))
    float x2 = x * x;
    float arg = x * fmaf(-0.1029392175f, x2, -2.302118149f);
    float den = ex2_approx(arg) + 1.0f;
    return x * rcp_approx(den);
}

__device__ __forceinline__ float sigmoid_f(float x) {
    float den = ex2_approx(x * -1.442695041f) + 1.0f;
    return rcp_approx(den);
}

__global__ void zero_acc_kernel() {
    int i = threadIdx.x;
    if (i < 52) g_acc[i] = 0.0;
}

__device__ __forceinline__ void load_hrow(float h[4], const float* row, bool bdry, float NINF) {
    float4 c = *(const float4*)row;
    float lf = row[-1], rg = row[4];
    if (bdry) {
        lf  = (lf  < 1e30f) ? lf  : NINF;
        c.x = (c.x < 1e30f) ? c.x : NINF;
        c.y = (c.y < 1e30f) ? c.y : NINF;
        c.z = (c.z < 1e30f) ? c.z : NINF;
        c.w = (c.w < 1e30f) ? c.w : NINF;
        rg  = (rg  < 1e30f) ? rg  : NINF;
    }
    h[0] = fmaxf(lf,  fmaxf(c.x, c.y));
    h[1] = fmaxf(c.x, fmaxf(c.y, c.z));
    h[2] = fmaxf(c.y, fmaxf(c.z, c.w));
    h[3] = fmaxf(c.z, fmaxf(c.w, rg));
}

__global__ __launch_bounds__(NTHREADS, 4)
void cldice_main(const float* __restrict__ y_pred, const float* __restrict__ y_true) {
    __shared__ float bufA[NROWS * SX];
    __shared__ float bufB[NROWS * SX];
    __shared__ float red[8][8];

    const int tid = threadIdx.x;
    const int gx0 = blockIdx.x * TILE, gy0 = blockIdx.y * TILE, b = blockIdx.z;
    const int base = b * (H * W);
    const bool bdry = (blockIdx.x == 0) | (blockIdx.x == (W/TILE - 1)) |
                      (blockIdx.y == 0) | (blockIdx.y == (H/TILE - 1));

    // 4x4 output block per thread: 16 blocks in x, 16 in y
    const int tx4 = tid & 15, ty4 = tid >> 4;
    const int sx = XOFF + tx4 * 4, sy = YOFF + ty4 * 4;

    // buffer coords valid iff gx0 + x - XOFF in [0,W) etc.
    const int xv_lo = XOFF - gx0;
    const int xv_hi = XOFF + (W - 1) - gx0;
    const int yv_lo = YOFF - gy0;
    const int yv_hi = YOFF + (H - 1) - gy0;

    // erode loop start indices (256 = 14*18 + 4)
    const int ery0 = tid / 18;
    const int erx0 = tid - ery0 * 18;

    float skel[16];
    float accA = 0.f, accB = 0.f, accC = 0.f, accD = 0.f;
    float accI = 0.f, accP = 0.f, accT = 0.f;

    const float INF = __int_as_float(0x7f800000);
    const float NINF = __int_as_float(0xff800000);

    #pragma unroll 1
    for (int t = 0; t < 2; ++t) {
        const float* src = t ? y_true : y_pred;
        float* b0 = bufA;
        float* b1 = bufB;

        // ---- load 74x74 halo tile into buffer x in [3,76], y in [0,73]; OOB -> +INF ----
        for (int i = tid; i < 74 * 74; i += NTHREADS) {
            int yy = i / 74, xx = i - yy * 74;
            int x = xx + 3;
            int gy = gy0 + yy - YOFF, gx = gx0 + x - XOFF;
            bool ok = (gy >= 0) & (gy < H) & (gx >= 0) & (gx < W);
            b0[yy * SX + x] = ok ? __ldg(src + base + gy * W + gx) : INF;
        }
        __syncthreads();

        #pragma unroll 1
        for (int lvl = 0; lvl < 4; ++lvl) {
            // ---- erode (plus-min), float4-vectorized, inline bdry fixup ----
            // region: y in [1+lvl, 72-lvl], x chunks at 4,8,...,72
            const int yl = 1 + lvl;
            const int ny = 72 - 2 * lvl;
            int ry = ery0, rx = erx0;
            while (ry < ny) {
                int x4 = 4 + rx * 4;
                int y = yl + ry;
                const float* rc = b0 + y * SX + x4;
                float4 c = *(const float4*)rc;
                float4 u = *(const float4*)(rc - SX);
                float4 d = *(const float4*)(rc + SX);
                float lft = rc[-1], rgt = rc[4];
                float4 o;
                o.x = fminf(fminf(c.x, fminf(lft, c.y)), fminf(u.x, d.x));
                o.y = fminf(fminf(c.y, fminf(c.x, c.z)), fminf(u.y, d.y));
                o.z = fminf(fminf(c.z, fminf(c.y, c.w)), fminf(u.z, d.z));
                o.w = fminf(fminf(c.w, fminf(c.z, rgt)), fminf(u.w, d.w));
                if (bdry) {
                    // out-of-image positions stay +INF
                    bool yok = (y >= yv_lo) & (y <= yv_hi);
                    o.x = (yok & (x4 + 0 >= xv_lo) & (x4 + 0 <= xv_hi)) ? o.x : INF;
                    o.y = (yok & (x4 + 1 >= xv_lo) & (x4 + 1 <= xv_hi)) ? o.y : INF;
                    o.z = (yok & (x4 + 2 >= xv_lo) & (x4 + 2 <= xv_hi)) ? o.z : INF;
                    o.w = (yok & (x4 + 3 >= xv_lo) & (x4 + 3 <= xv_hi)) ? o.w : INF;
                }
                *(float4*)(b1 + y * SX + x4) = o;
                rx += 4; ry += 14;
                if (rx >= 18) { rx -= 18; ry += 1; }
            }
            __syncthreads();

            // ---- dilate 3x3 (rolling 3-row window) + delta + skel update ----
            float h0[4], h1[4], h2[4];
            load_hrow(h0, b1 + (sy - 1) * SX + sx, bdry, NINF);
            load_hrow(h1, b1 + sy * SX + sx, bdry, NINF);
            #pragma unroll
            for (int r = 0; r < 4; ++r) {
                load_hrow(h2, b1 + (sy + 1 + r) * SX + sx, bdry, NINF);
                const float4 a4 = *(const float4*)(b0 + (sy + r) * SX + sx);
                float av[4] = {a4.x, a4.y, a4.z, a4.w};
                float4 t4;
                if (lvl == 0 && t == 0) {
                    t4 = *(const float4*)(y_true + base + (gy0 + sy - YOFF + r) * W
                                          + gx0 + sx - XOFF);
                }
                #pragma unroll
                for (int c = 0; c < 4; ++c) {
                    float m = fmaxf(h0[c], fmaxf(h1[c], h2[c]));
                    float a = av[c];
                    float delta = gelu_f(a - m);
                    int j = r * 4 + c;
                    if (lvl == 0) {
                        skel[j] = delta;
                        if (t == 0) {
                            float tval = (c == 0) ? t4.x : (c == 1) ? t4.y
                                       : (c == 2) ? t4.z : t4.w;
                            float s = sigmoid_f(a);
                            accI += s * tval;
                            accP += s;
                            accT += tval;
                        }
                    } else {
                        skel[j] += gelu_f(delta - skel[j] * delta);
                    }
                }
                #pragma unroll
                for (int c = 0; c < 4; ++c) { h0[c] = h1[c]; h1[c] = h2[c]; }
            }
            __syncthreads();
            float* tmp = b0; b0 = b1; b1 = tmp;
        }

        // ---- accumulate skel sums; partner image re-read from gmem (L2) ----
        const float* partner = t ? y_pred : y_true;
        #pragma unroll
        for (int r = 0; r < 4; ++r) {
            const float4 p4 = *(const float4*)(partner + base + (gy0 + sy - YOFF + r) * W
                                               + gx0 + sx - XOFF);
            float pvv[4] = {p4.x, p4.y, p4.z, p4.w};
            #pragma unroll
            for (int c = 0; c < 4; ++c) {
                int j = r * 4 + c;
                if (t == 0) { accA += skel[j] * pvv[c]; accB += skel[j]; }
                else        { accC += skel[j] * pvv[c]; accD += skel[j]; }
            }
        }
    }

    // ---- block reduction of 7 partials, then one double atomic each ----
    float vals[7] = {accA, accB, accC, accD, accI, accP, accT};
    int lane = tid & 31, warp = tid >> 5;
    #pragma unroll
    for (int k = 0; k < 7; ++k) {
        float v = vals[k];
        #pragma unroll
        for (int o = 16; o > 0; o >>= 1) v += __shfl_down_sync(0xffffffffu, v, o);
        if (lane == 0) red[warp][k] = v;
    }
    __syncthreads();
    if (warp == 0 && lane < 7) {
        float s = 0.f;
        #pragma unroll
        for (int w = 0; w < 8; ++w) s += red[w][lane];
        int idx = (lane < 4) ? lane : (4 + (lane - 4) * 16 + b);
        atomicAdd(&g_acc[idx], (double)s);
    }
}

__global__ void finalize_kernel(float* out, int n) {
    if (threadIdx.x == 0) {
        double A = g_acc[0], B = g_acc[1], C = g_acc[2], D = g_acc[3];
        double tprec = (A + 1.0) / (B + 1.0);
        double tsens = (C + 1.0) / (D + 1.0);
        double cl = 1.0 - 2.0 * (tprec * tsens) / (tprec + tsens);
        double dsum = 0.0;
        for (int i = 0; i < 16; ++i) {
            double gd = (2.0 * g_acc[4 + i] + 1e-4) / (g_acc[20 + i] + g_acc[36 + i] + 1e-4);
            dsum += 1.0 - gd;
        }
        double dice = dsum / 16.0;
        double res = 0.5 * cl + 0.5 * dice;
        for (int i = 0; i < n; ++i) out[i] = (float)res;
    }
}

extern "C" void kernel_launch(void* const* d_in, const int* in_sizes, int n_in,
                              void* d_out, int out_size) {
    const float* y_pred = (const float*)d_in[0];
    const float* y_true = (const float*)d_in[1];
    (void)in_sizes; (void)n_in;

    zero_acc_kernel<<<1, 64>>>();
    dim3 grid(W / TILE, H / TILE, NB);
    cldice_main<<<grid, NTHREADS>>>(y_pred, y_true);
    finalize_kernel<<<1, 32>>>((float*)d_out, out_size);
}

// round 8
// speedup vs baseline: 2.0815x; 1.0463x over previous
#include <cuda_runtime.h>

#define H 1024
#define W 1024
#define NB 16
#define TILE 64
#define XOFF 8          // tile col 0 sits at buffer x=8 (so tile cols are 4-aligned)
#define YOFF 5
#define SX 80           // buffer row stride (floats)
#define NROWS 74
#define NTHREADS 256

// accumulators: [0]=A sum skel_p*t, [1]=B sum skel_p, [2]=C sum skel_t*p, [3]=D sum skel_t,
// [4+b]=inter_b, [20+b]=sum_sig_p_b, [36+b]=sum_t_b
__device__ double g_acc[52];

__device__ __forceinline__ float ex2_approx(float x) {
    float r;
    asm("ex2.approx.ftz.f32 %0, %1;" : "=f"(r) : "f"(x));
    return r;
}
__device__ __forceinline__ float rcp_approx(float x) {
    float r;
    asm("rcp.approx.ftz.f32 %0, %1;" : "=f"(r) : "f"(x));
    return r;
}
__device__ __forceinline__ float tanh_approx(float x) {
    float r;
    asm("tanh.approx.f32 %0, %1;" : "=f"(r) : "f"(x));
    return r;
}

__device__ __forceinline__ float gelu_f(float x) {
    // tanh-form gelu with HW tanh: gelu(x) = 0.5x * (1 + tanh(0.79788456*(x + 0.044715 x^3)))
    float x2 = x * x;
    float y = x * fmaf(0.0356774081f, x2, 0.7978845608f);
    float hx = 0.5f * x;
    return fmaf(hx, tanh_approx(y), hx);
}

__device__ __forceinline__ float sigmoid_f(float x) {
    float den = ex2_approx(x * -1.442695041f) + 1.0f;
    return rcp_approx(den);
}

__global__ void zero_acc_kernel() {
    int i = threadIdx.x;
    if (i < 52) g_acc[i] = 0.0;
}

__device__ __forceinline__ void load_hrow(float h[4], const float* row, bool bdry, float NINF) {
    float4 c = *(const float4*)row;
    float lf = row[-1], rg = row[4];
    if (bdry) {
        lf  = (lf  < 1e30f) ? lf  : NINF;
        c.x = (c.x < 1e30f) ? c.x : NINF;
        c.y = (c.y < 1e30f) ? c.y : NINF;
        c.z = (c.z < 1e30f) ? c.z : NINF;
        c.w = (c.w < 1e30f) ? c.w : NINF;
        rg  = (rg  < 1e30f) ? rg  : NINF;
    }
    h[0] = fmaxf(lf,  fmaxf(c.x, c.y));
    h[1] = fmaxf(c.x, fmaxf(c.y, c.z));
    h[2] = fmaxf(c.y, fmaxf(c.z, c.w));
    h[3] = fmaxf(c.z, fmaxf(c.w, rg));
}

__global__ __launch_bounds__(NTHREADS, 4)
void cldice_main(const float* __restrict__ y_pred, const float* __restrict__ y_true) {
    __shared__ float bufA[NROWS * SX];
    __shared__ float bufB[NROWS * SX];
    __shared__ float red[8][8];

    const int tid = threadIdx.x;
    const int gx0 = blockIdx.x * TILE, gy0 = blockIdx.y * TILE, b = blockIdx.z;
    const int base = b * (H * W);
    const bool bdry = (blockIdx.x == 0) | (blockIdx.x == (W/TILE - 1)) |
                      (blockIdx.y == 0) | (blockIdx.y == (H/TILE - 1));

    // 4x4 output block per thread: 16 blocks in x, 16 in y
    const int tx4 = tid & 15, ty4 = tid >> 4;
    const int sx = XOFF + tx4 * 4, sy = YOFF + ty4 * 4;

    // buffer coords valid iff gx0 + x - XOFF in [0,W) etc.
    const int xv_lo = XOFF - gx0;
    const int xv_hi = XOFF + (W - 1) - gx0;
    const int yv_lo = YOFF - gy0;
    const int yv_hi = YOFF + (H - 1) - gy0;

    // erode loop start indices
    const int ery0 = tid / 18;
    const int erx0 = tid - ery0 * 18;

    float skel[16];
    float accA = 0.f, accB = 0.f, accC = 0.f, accD = 0.f;
    float accI = 0.f, accP = 0.f, accT = 0.f;

    const float INF = __int_as_float(0x7f800000);
    const float NINF = __int_as_float(0xff800000);

    #pragma unroll 1
    for (int t = 0; t < 2; ++t) {
        const float* src = t ? y_true : y_pred;
        float* b0 = bufA;
        float* b1 = bufB;

        // ---- load 74x74 halo tile into buffer x in [3,76], y in [0,73]; OOB -> +INF ----
        for (int i = tid; i < 74 * 74; i += NTHREADS) {
            int yy = i / 74, xx = i - yy * 74;
            int x = xx + 3;
            int gy = gy0 + yy - YOFF, gx = gx0 + x - XOFF;
            bool ok = (gy >= 0) & (gy < H) & (gx >= 0) & (gx < W);
            b0[yy * SX + x] = ok ? __ldg(src + base + gy * W + gx) : INF;
        }
        __syncthreads();

        #pragma unroll 1
        for (int lvl = 0; lvl < 4; ++lvl) {
            // ---- erode (plus-min), float4-vectorized, inline bdry fixup ----
            const int yl = 1 + lvl;
            const int ny = 72 - 2 * lvl;
            int ry = ery0, rx = erx0;
            while (ry < ny) {
                int x4 = 4 + rx * 4;
                int y = yl + ry;
                const float* rc = b0 + y * SX + x4;
                float4 c = *(const float4*)rc;
                float4 u = *(const float4*)(rc - SX);
                float4 d = *(const float4*)(rc + SX);
                float lft = rc[-1], rgt = rc[4];
                float4 o;
                o.x = fminf(fminf(c.x, fminf(lft, c.y)), fminf(u.x, d.x));
                o.y = fminf(fminf(c.y, fminf(c.x, c.z)), fminf(u.y, d.y));
                o.z = fminf(fminf(c.z, fminf(c.y, c.w)), fminf(u.z, d.z));
                o.w = fminf(fminf(c.w, fminf(c.z, rgt)), fminf(u.w, d.w));
                if (bdry) {
                    bool yok = (y >= yv_lo) & (y <= yv_hi);
                    o.x = (yok & (x4 + 0 >= xv_lo) & (x4 + 0 <= xv_hi)) ? o.x : INF;
                    o.y = (yok & (x4 + 1 >= xv_lo) & (x4 + 1 <= xv_hi)) ? o.y : INF;
                    o.z = (yok & (x4 + 2 >= xv_lo) & (x4 + 2 <= xv_hi)) ? o.z : INF;
                    o.w = (yok & (x4 + 3 >= xv_lo) & (x4 + 3 <= xv_hi)) ? o.w : INF;
                }
                *(float4*)(b1 + y * SX + x4) = o;
                rx += 4; ry += 14;
                if (rx >= 18) { rx -= 18; ry += 1; }
            }
            __syncthreads();

            // ---- dilate 3x3 (rolling 3-row window) + delta + skel update ----
            float h0[4], h1[4], h2[4];
            load_hrow(h0, b1 + (sy - 1) * SX + sx, bdry, NINF);
            load_hrow(h1, b1 + sy * SX + sx, bdry, NINF);
            #pragma unroll
            for (int r = 0; r < 4; ++r) {
                load_hrow(h2, b1 + (sy + 1 + r) * SX + sx, bdry, NINF);
                const float4 a4 = *(const float4*)(b0 + (sy + r) * SX + sx);
                float av[4] = {a4.x, a4.y, a4.z, a4.w};
                #pragma unroll
                for (int c = 0; c < 4; ++c) {
                    float m = fmaxf(h0[c], fmaxf(h1[c], h2[c]));
                    float delta = gelu_f(av[c] - m);
                    int j = r * 4 + c;
                    if (lvl == 0) skel[j] = delta;
                    else          skel[j] += gelu_f(delta - skel[j] * delta);
                }
                #pragma unroll
                for (int c = 0; c < 4; ++c) { h0[c] = h1[c]; h1[c] = h2[c]; }
            }
            __syncthreads();
            float* tmp = b0; b0 = b1; b1 = tmp;
        }

        // ---- epilogue: accumulate skel sums + dice terms from gmem (L2-hot) ----
        #pragma unroll
        for (int r = 0; r < 4; ++r) {
            const int goff = base + (gy0 + sy - YOFF + r) * W + gx0 + sx - XOFF;
            if (t == 0) {
                const float4 t4 = *(const float4*)(y_true + goff);
                const float4 q4 = *(const float4*)(y_pred + goff);
                float tvv[4] = {t4.x, t4.y, t4.z, t4.w};
                float qvv[4] = {q4.x, q4.y, q4.z, q4.w};
                #pragma unroll
                for (int c = 0; c < 4; ++c) {
                    int j = r * 4 + c;
                    accA += skel[j] * tvv[c];
                    accB += skel[j];
                    float s = sigmoid_f(qvv[c]);
                    accI += s * tvv[c];
                    accP += s;
                    accT += tvv[c];
                }
            } else {
                const float4 p4 = *(const float4*)(y_pred + goff);
                float pvv[4] = {p4.x, p4.y, p4.z, p4.w};
                #pragma unroll
                for (int c = 0; c < 4; ++c) {
                    int j = r * 4 + c;
                    accC += skel[j] * pvv[c];
                    accD += skel[j];
                }
            }
        }
    }

    // ---- block reduction of 7 partials, then one double atomic each ----
    float vals[7] = {accA, accB, accC, accD, accI, accP, accT};
    int lane = tid & 31, warp = tid >> 5;
    #pragma unroll
    for (int k = 0; k < 7; ++k) {
        float v = vals[k];
        #pragma unroll
        for (int o = 16; o > 0; o >>= 1) v += __shfl_down_sync(0xffffffffu, v, o);
        if (lane == 0) red[warp][k] = v;
    }
    __syncthreads();
    if (warp == 0 && lane < 7) {
        float s = 0.f;
        #pragma unroll
        for (int w = 0; w < 8; ++w) s += red[w][lane];
        int idx = (lane < 4) ? lane : (4 + (lane - 4) * 16 + b);
        atomicAdd(&g_acc[idx], (double)s);
    }
}

__global__ void finalize_kernel(float* out, int n) {
    if (threadIdx.x == 0) {
        double A = g_acc[0], B = g_acc[1], C = g_acc[2], D = g_acc[3];
        double tprec = (A + 1.0) / (B + 1.0);
        double tsens = (C + 1.0) / (D + 1.0);
        double cl = 1.0 - 2.0 * (tprec * tsens) / (tprec + tsens);
        double dsum = 0.0;
        for (int i = 0; i < 16; ++i) {
            double gd = (2.0 * g_acc[4 + i] + 1e-4) / (g_acc[20 + i] + g_acc[36 + i] + 1e-4);
            dsum += 1.0 - gd;
        }
        double dice = dsum / 16.0;
        double res = 0.5 * cl + 0.5 * dice;
        for (int i = 0; i < n; ++i) out[i] = (float)res;
    }
}

extern "C" void kernel_launch(void* const* d_in, const int* in_sizes, int n_in,
                              void* d_out, int out_size) {
    const float* y_pred = (const float*)d_in[0];
    const float* y_true = (const float*)d_in[1];
    (void)in_sizes; (void)n_in;

    zero_acc_kernel<<<1, 64>>>();
    dim3 grid(W / TILE, H / TILE, NB);
    cldice_main<<<grid, NTHREADS>>>(y_pred, y_true);
    finalize_kernel<<<1, 32>>>((float*)d_out, out_size);
}

// round 9
// speedup vs baseline: 2.1899x; 1.0521x over previous
#include <cuda_runtime.h>

#define H 1024
#define W 1024
#define NB 16
#define TILE 64
#define XOFF 8          // tile col 0 sits at buffer x=8 (so tile cols are 4-aligned)
#define YOFF 5
#define SX 80           // buffer row stride (floats)
#define NROWS 74
#define NTHREADS 256
#define NSTRIP 14       // erode y-strips (18 x-chunks * 14 strips = 252 threads)

// accumulators: [0]=A sum skel_p*t, [1]=B sum skel_p, [2]=C sum skel_t*p, [3]=D sum skel_t,
// [4+b]=inter_b, [20+b]=sum_sig_p_b, [36+b]=sum_t_b
__device__ double g_acc[52];

__device__ __forceinline__ float ex2_approx(float x) {
    float r;
    asm("ex2.approx.ftz.f32 %0, %1;" : "=f"(r) : "f"(x));
    return r;
}
__device__ __forceinline__ float rcp_approx(float x) {
    float r;
    asm("rcp.approx.ftz.f32 %0, %1;" : "=f"(r) : "f"(x));
    return r;
}
__device__ __forceinline__ float tanh_approx(float x) {
    float r;
    asm("tanh.approx.f32 %0, %1;" : "=f"(r) : "f"(x));
    return r;
}

__device__ __forceinline__ float gelu_f(float x) {
    // tanh-form gelu with HW tanh: gelu(x) = 0.5x * (1 + tanh(0.79788456*(x + 0.044715 x^3)))
    float x2 = x * x;
    float y = x * fmaf(0.0356774081f, x2, 0.7978845608f);
    float hx = 0.5f * x;
    return fmaf(hx, tanh_approx(y), hx);
}

__device__ __forceinline__ float sigmoid_f(float x) {
    float den = ex2_approx(x * -1.442695041f) + 1.0f;
    return rcp_approx(den);
}

__global__ void zero_acc_kernel() {
    int i = threadIdx.x;
    if (i < 52) g_acc[i] = 0.0;
}

__device__ __forceinline__ void load_hrow(float h[4], const float* row, bool bdry, float NINF) {
    float4 c = *(const float4*)row;
    float lf = row[-1], rg = row[4];
    if (bdry) {
        lf  = (lf  < 1e30f) ? lf  : NINF;
        c.x = (c.x < 1e30f) ? c.x : NINF;
        c.y = (c.y < 1e30f) ? c.y : NINF;
        c.z = (c.z < 1e30f) ? c.z : NINF;
        c.w = (c.w < 1e30f) ? c.w : NINF;
        rg  = (rg  < 1e30f) ? rg  : NINF;
    }
    h[0] = fmaxf(lf,  fmaxf(c.x, c.y));
    h[1] = fmaxf(c.x, fmaxf(c.y, c.z));
    h[2] = fmaxf(c.y, fmaxf(c.z, c.w));
    h[3] = fmaxf(c.z, fmaxf(c.w, rg));
}

__global__ __launch_bounds__(NTHREADS, 4)
void cldice_main(const float* __restrict__ y_pred, const float* __restrict__ y_true) {
    __shared__ float bufA[NROWS * SX];
    __shared__ float bufB[NROWS * SX];
    __shared__ float red[8][8];

    const int tid = threadIdx.x;
    const int gx0 = blockIdx.x * TILE, gy0 = blockIdx.y * TILE, b = blockIdx.z;
    const int base = b * (H * W);
    const bool bdry = (blockIdx.x == 0) | (blockIdx.x == (W/TILE - 1)) |
                      (blockIdx.y == 0) | (blockIdx.y == (H/TILE - 1));

    // 4x4 output block per thread: 16 blocks in x, 16 in y
    const int tx4 = tid & 15, ty4 = tid >> 4;
    const int sx = XOFF + tx4 * 4, sy = YOFF + ty4 * 4;

    // buffer coords valid iff gx0 + x - XOFF in [0,W) etc.
    const int xv_lo = XOFF - gx0;
    const int xv_hi = XOFF + (W - 1) - gx0;
    const int yv_lo = YOFF - gy0;
    const int yv_hi = YOFF + (H - 1) - gy0;

    // erode strip mapping: 18 x-chunks * 14 y-strips
    const int ys = tid / 18;              // 0..14 (>=14 -> idle)
    const int xc = tid - ys * 18;
    const int ex4 = 4 + xc * 4;           // x in [4,75]

    float skel[16];
    float accA = 0.f, accB = 0.f, accC = 0.f, accD = 0.f;
    float accI = 0.f, accP = 0.f, accT = 0.f;

    const float INF = __int_as_float(0x7f800000);
    const float NINF = __int_as_float(0xff800000);

    #pragma unroll 1
    for (int t = 0; t < 2; ++t) {
        const float* src = t ? y_true : y_pred;
        float* b0 = bufA;
        float* b1 = bufB;

        // ---- load 74x74 halo tile into buffer x in [3,76], y in [0,73]; OOB -> +INF ----
        for (int i = tid; i < 74 * 74; i += NTHREADS) {
            int yy = i / 74, xx = i - yy * 74;
            int x = xx + 3;
            int gy = gy0 + yy - YOFF, gx = gx0 + x - XOFF;
            bool ok = (gy >= 0) & (gy < H) & (gx >= 0) & (gx < W);
            b0[yy * SX + x] = ok ? __ldg(src + base + gy * W + gx) : INF;
        }
        __syncthreads();

        #pragma unroll 1
        for (int lvl = 0; lvl < 4; ++lvl) {
            // ---- erode (plus-min): strip-based rolling 3-row window ----
            // region: y in [yl, yl+ny-1], x chunks at ex4
            const int yl = 1 + lvl;
            const int ny = 72 - 2 * lvl;
            int rows = 0, y0 = 0;
            if (ys < NSTRIP) {
                int bse = ny / NSTRIP, rem = ny - bse * NSTRIP;
                rows = bse + (ys < rem ? 1 : 0);
                y0 = yl + ys * bse + (ys < rem ? ys : rem);
            }
            if (rows > 0) {
                const float* pbase = b0 + y0 * SX + ex4;
                float4 uc = *(const float4*)(pbase - SX);   // row y0-1 center
                float4 pc = *(const float4*)pbase;          // row y0 center
                float pl = pbase[-1], pr = pbase[4];
                #pragma unroll 1
                for (int r = 0; r < rows; ++r) {
                    const float* nrow = b0 + (y0 + r + 1) * SX + ex4;
                    float4 nc = *(const float4*)nrow;
                    float nl = nrow[-1], nr2 = nrow[4];
                    float4 o;
                    o.x = fminf(fminf(pc.x, fminf(pl,   pc.y)), fminf(uc.x, nc.x));
                    o.y = fminf(fminf(pc.y, fminf(pc.x, pc.z)), fminf(uc.y, nc.y));
                    o.z = fminf(fminf(pc.z, fminf(pc.y, pc.w)), fminf(uc.z, nc.z));
                    o.w = fminf(fminf(pc.w, fminf(pc.z, pr  )), fminf(uc.w, nc.w));
                    int y = y0 + r;
                    if (bdry) {
                        bool yok = (y >= yv_lo) & (y <= yv_hi);
                        o.x = (yok & (ex4 + 0 >= xv_lo) & (ex4 + 0 <= xv_hi)) ? o.x : INF;
                        o.y = (yok & (ex4 + 1 >= xv_lo) & (ex4 + 1 <= xv_hi)) ? o.y : INF;
                        o.z = (yok & (ex4 + 2 >= xv_lo) & (ex4 + 2 <= xv_hi)) ? o.z : INF;
                        o.w = (yok & (ex4 + 3 >= xv_lo) & (ex4 + 3 <= xv_hi)) ? o.w : INF;
                    }
                    *(float4*)(b1 + y * SX + ex4) = o;
                    uc = pc; pc = nc; pl = nl; pr = nr2;
                }
            }
            __syncthreads();

            // ---- dilate 3x3 (rolling 3-row window) + delta + skel update ----
            float h0[4], h1[4], h2[4];
            load_hrow(h0, b1 + (sy - 1) * SX + sx, bdry, NINF);
            load_hrow(h1, b1 + sy * SX + sx, bdry, NINF);
            #pragma unroll
            for (int r = 0; r < 4; ++r) {
                load_hrow(h2, b1 + (sy + 1 + r) * SX + sx, bdry, NINF);
                const float4 a4 = *(const float4*)(b0 + (sy + r) * SX + sx);
                float av[4] = {a4.x, a4.y, a4.z, a4.w};
                #pragma unroll
                for (int c = 0; c < 4; ++c) {
                    float m = fmaxf(h0[c], fmaxf(h1[c], h2[c]));
                    float delta = gelu_f(av[c] - m);
                    int j = r * 4 + c;
                    if (lvl == 0) skel[j] = delta;
                    else          skel[j] += gelu_f(delta - skel[j] * delta);
                }
                #pragma unroll
                for (int c = 0; c < 4; ++c) { h0[c] = h1[c]; h1[c] = h2[c]; }
            }
            __syncthreads();
            float* tmp = b0; b0 = b1; b1 = tmp;
        }

        // ---- epilogue: accumulate skel sums + dice terms from gmem (L2-hot) ----
        #pragma unroll
        for (int r = 0; r < 4; ++r) {
            const int goff = base + (gy0 + sy - YOFF + r) * W + gx0 + sx - XOFF;
            if (t == 0) {
                const float4 t4 = *(const float4*)(y_true + goff);
                const float4 q4 = *(const float4*)(y_pred + goff);
                float tvv[4] = {t4.x, t4.y, t4.z, t4.w};
                float qvv[4] = {q4.x, q4.y, q4.z, q4.w};
                #pragma unroll
                for (int c = 0; c < 4; ++c) {
                    int j = r * 4 + c;
                    accA += skel[j] * tvv[c];
                    accB += skel[j];
                    float s = sigmoid_f(qvv[c]);
                    accI += s * tvv[c];
                    accP += s;
                    accT += tvv[c];
                }
            } else {
                const float4 p4 = *(const float4*)(y_pred + goff);
                float pvv[4] = {p4.x, p4.y, p4.z, p4.w};
                #pragma unroll
                for (int c = 0; c < 4; ++c) {
                    int j = r * 4 + c;
                    accC += skel[j] * pvv[c];
                    accD += skel[j];
                }
            }
        }
    }

    // ---- block reduction of 7 partials, then one double atomic each ----
    float vals[7] = {accA, accB, accC, accD, accI, accP, accT};
    int lane = tid & 31, warp = tid >> 5;
    #pragma unroll
    for (int k = 0; k < 7; ++k) {
        float v = vals[k];
        #pragma unroll
        for (int o = 16; o > 0; o >>= 1) v += __shfl_down_sync(0xffffffffu, v, o);
        if (lane == 0) red[warp][k] = v;
    }
    __syncthreads();
    if (warp == 0 && lane < 7) {
        float s = 0.f;
        #pragma unroll
        for (int w = 0; w < 8; ++w) s += red[w][lane];
        int idx = (lane < 4) ? lane : (4 + (lane - 4) * 16 + b);
        atomicAdd(&g_acc[idx], (double)s);
    }
}

__global__ void finalize_kernel(float* out, int n) {
    if (threadIdx.x == 0) {
        double A = g_acc[0], B = g_acc[1], C = g_acc[2], D = g_acc[3];
        double tprec = (A + 1.0) / (B + 1.0);
        double tsens = (C + 1.0) / (D + 1.0);
        double cl = 1.0 - 2.0 * (tprec * tsens) / (tprec + tsens);
        double dsum = 0.0;
        for (int i = 0; i < 16; ++i) {
            double gd = (2.0 * g_acc[4 + i] + 1e-4) / (g_acc[20 + i] + g_acc[36 + i] + 1e-4);
            dsum += 1.0 - gd;
        }
        double dice = dsum / 16.0;
        double res = 0.5 * cl + 0.5 * dice;
        for (int i = 0; i < n; ++i) out[i] = (float)res;
    }
}

extern "C" void kernel_launch(void* const* d_in, const int* in_sizes, int n_in,
                              void* d_out, int out_size) {
    const float* y_pred = (const float*)d_in[0];
    const float* y_true = (const float*)d_in[1];
    (void)in_sizes; (void)n_in;

    zero_acc_kernel<<<1, 64>>>();
    dim3 grid(W / TILE, H / TILE, NB);
    cldice_main<<<grid, NTHREADS>>>(y_pred, y_true);
    finalize_kernel<<<1, 32>>>((float*)d_out, out_size);
}